// round 2
// baseline (speedup 1.0000x reference)
#include <cuda_runtime.h>
#include <cstdint>

#define BB   2048
#define TTd  200
#define FSZ  128
#define H1N  80
#define H2N  40
#define KC   32
#define NCH  4
#define NEG_BIG_F (-4294967295.0f)

// ---- shared memory float offsets for k_scores ----
#define OF_SF    0        // 2 * 32 * 200 = 12800
#define OF_SMT   12800    // 128*80 = 10240
#define OF_SH1   23040    // 200*82 = 16400
#define OF_SW2   39440    // 80*40 = 3200
#define OF_SPART 42640    // 10*200 = 2000
#define OF_SQ    44640    // 128
#define OF_SCB   44768    // 80
#define OF_RED   44848    // 32
#define SMEM_FLOATS 44880 // *4 = 179,520 bytes

// ---- device scratch (static, no runtime allocation) ----
__device__ float g_q  [BB * FSZ];
__device__ float g_cb [BB * H1N];
__device__ float g_AT [FSZ * H1N];
__device__ float g_BmT[FSZ * H1N];
__device__ float g_C2T[FSZ * H1N];
__device__ float g_WqT[FSZ * FSZ];
__device__ int   g_maskI32;   // 1 if mask buffer is int32 0/1, 0 if byte mask

// packed fp32x2 helpers (Blackwell paired FP32 — 2x scalar FFMA throughput)
__device__ __forceinline__ void fma2(unsigned long long &d,
                                     unsigned long long a,
                                     unsigned long long b) {
    asm("fma.rn.f32x2 %0, %1, %2, %0;" : "+l"(d) : "l"(a), "l"(b));
}
__device__ __forceinline__ unsigned long long dup2(float x) {
    unsigned long long r;
    asm("mov.b64 %0, {%1, %1};" : "=l"(r) : "f"(x));
    return r;
}
__device__ __forceinline__ float sigf(float x) {
    return 1.0f / (1.0f + __expf(-x));
}

// ============================================================
// Kernel 0: mask dtype probe. JAX bool may arrive as int32 (LE 0/1)
// or as a byte mask. If int32, every byte at index i%4 != 0 within the
// first 4096 bytes is zero (prob ~0 for a random byte mask).
// Deterministic for fixed inputs; 4096 B is within either buffer size.
// ============================================================
__global__ void k_detect(const unsigned char* __restrict__ m) {
    __shared__ int bad;
    if (threadIdx.x == 0) bad = 0;
    __syncthreads();
    int acc = 0;
    for (int i = threadIdx.x; i < 4096; i += blockDim.x)
        if ((i & 3) && m[i]) acc = 1;
    if (acc) atomicOr(&bad, 1);
    __syncthreads();
    if (threadIdx.x == 0) g_maskI32 = bad ? 0 : 1;
}

// ============================================================
// Kernel 1: weight preprocessing.
//   A  = W1[:,0:128] + W1[:,256:384]   (applied to q)
//   Bm = W1[:,128:256] - W1[:,256:384] (applied to f)
//   C2 = W1[:,384:512]                 (applied to q*f)
// stored TRANSPOSED: X_T[d*80 + h] for coalesced consumption.
// Also WqT[k*128+d] = Wq[d*128+k].
// ============================================================
__global__ void k_prep(const float* __restrict__ W1, const float* __restrict__ Wq) {
    int idx = blockIdx.x * blockDim.x + threadIdx.x;
    if (idx < FSZ * H1N) {
        int d = idx / H1N, h = idx - d * H1N;
        const float* r = W1 + (size_t)h * 4 * FSZ;
        float w0 = r[d], w1 = r[FSZ + d], w2 = r[2 * FSZ + d], w3v = r[3 * FSZ + d];
        g_AT[idx]  = w0 + w2;
        g_BmT[idx] = w1 - w2;
        g_C2T[idx] = w3v;
    }
    if (idx < FSZ * FSZ) {
        int k = idx / FSZ, d = idx - k * FSZ;
        g_WqT[idx] = Wq[d * FSZ + k];
    }
}

// ============================================================
// Kernel 2: per-batch q = PReLU(query @ Wq^T + bq), c_b = q@A^T + b1
// ============================================================
__global__ void k_query(const float* __restrict__ query, const float* __restrict__ bq,
                        const float* __restrict__ aP, const float* __restrict__ b1) {
    __shared__ float sqr[FSZ];
    __shared__ float sqv[FSZ];
    int b = blockIdx.x, tid = threadIdx.x;
    sqr[tid] = query[(size_t)b * FSZ + tid];
    __syncthreads();
    float acc = 0.f;
#pragma unroll 8
    for (int k = 0; k < FSZ; k++) acc += sqr[k] * g_WqT[k * FSZ + tid];
    acc += bq[tid];
    float a = aP[0];
    float q = acc > 0.f ? acc : a * acc;
    g_q[(size_t)b * FSZ + tid] = q;
    sqv[tid] = q;
    __syncthreads();
    if (tid < H1N) {
        float c = 0.f;
#pragma unroll 8
        for (int d = 0; d < FSZ; d++) c += sqv[d] * g_AT[d * H1N + tid];
        g_cb[(size_t)b * H1N + tid] = c + b1[tid];
    }
}

// ============================================================
// Kernel 3: one CTA per batch. 256 threads (250 active in GEMM).
// Thread (rt, ch): rt = tid/10 in [0,25), ch = tid%10 in [0,10).
// GEMM1: H1[200x80] = sigmoid(F[200x128] @ M_b^T + c_b), 8x8 reg tile, f32x2
// GEMM2: H2[200x40] = sigmoid(H1 @ W2^T + b2),            8x4 reg tile, f32x2
// Stage3 + masked softmax -> scores.
// ============================================================
__global__ __launch_bounds__(256, 1)
void k_scores(const float* __restrict__ facts, const unsigned char* __restrict__ mask,
              const float* __restrict__ W2, const float* __restrict__ b2,
              const float* __restrict__ W3, const float* __restrict__ b3,
              float* __restrict__ scoresOut) {
    extern __shared__ float sm[];
    float* sF    = sm + OF_SF;     // [2][32][200] transposed facts chunks
    float* sMt   = sm + OF_SMT;    // [128][80]   M_b transposed
    float* sH1   = sm + OF_SH1;    // [200][82]
    float* sW2t  = sm + OF_SW2;    // [80][40]
    float* sPart = sm + OF_SPART;  // [10][200]
    float* sq    = sm + OF_SQ;
    float* scb   = sm + OF_SCB;
    float* red   = sm + OF_RED;

    int b = blockIdx.x, tid = threadIdx.x;
    bool active = tid < 250;
    int rt = tid / 10, ch = tid - rt * 10;

    // -------- prelude --------
    if (tid < FSZ) sq[tid]  = g_q[(size_t)b * FSZ + tid];
    if (tid < H1N) scb[tid] = g_cb[(size_t)b * H1N + tid];
    for (int i = tid; i < H2N * H1N; i += 256) {       // W2t[k][j] = W2[j][k]
        int j = i / H1N, k = i - j * H1N;
        sW2t[k * H2N + j] = W2[i];
    }
    __syncthreads();

    const float4* factsB = (const float4*)(facts + (size_t)b * TTd * FSZ);

    // chunk 0 global loads + M_b build, then transpose-store chunk 0
    float4 pf[7];
#pragma unroll
    for (int r = 0; r < 7; r++) {
        int i = tid + r * 256;
        if (i < 1600) { int t = i >> 3, j = i & 7; pf[r] = factsB[t * 32 + j]; }
    }
    for (int i = tid; i < FSZ * H1N; i += 256)
        sMt[i] = g_BmT[i] + sq[i / H1N] * g_C2T[i];
#pragma unroll
    for (int r = 0; r < 7; r++) {
        int i = tid + r * 256;
        if (i < 1600) {
            int t = i >> 3, j = i & 7;
            float* p = sF + (j * 4) * TTd + t;
            p[0] = pf[r].x; p[TTd] = pf[r].y; p[2 * TTd] = pf[r].z; p[3 * TTd] = pf[r].w;
        }
    }
    __syncthreads();

    // -------- GEMM1: acc[8 t][4 h-pairs], packed f32x2 --------
    unsigned long long acc[8][4];
#pragma unroll
    for (int i = 0; i < 8; i++)
#pragma unroll
        for (int j = 0; j < 4; j++) acc[i][j] = 0ull;

    for (int c = 0; c < NCH; c++) {
        const float* sFb = sF + (c & 1) * (KC * TTd);
        if (c < NCH - 1) {
#pragma unroll
            for (int r = 0; r < 7; r++) {
                int i = tid + r * 256;
                if (i < 1600) { int t = i >> 3, j = i & 7; pf[r] = factsB[t * 32 + (c + 1) * 8 + j]; }
            }
        }
        if (active) {
#pragma unroll 4
            for (int kk = 0; kk < KC; kk++) {
                const float* fb = sFb + kk * TTd + rt * 8;
                float4 f0 = *(const float4*)fb;
                float4 f1 = *(const float4*)(fb + 4);
                const ulonglong2* mp = (const ulonglong2*)(sMt + (c * KC + kk) * H1N + ch * 8);
                ulonglong2 mA = mp[0], mB = mp[1];
#define ROW1(i, fv) { unsigned long long a_ = dup2(fv); \
                      fma2(acc[i][0], a_, mA.x); fma2(acc[i][1], a_, mA.y); \
                      fma2(acc[i][2], a_, mB.x); fma2(acc[i][3], a_, mB.y); }
                ROW1(0, f0.x) ROW1(1, f0.y) ROW1(2, f0.z) ROW1(3, f0.w)
                ROW1(4, f1.x) ROW1(5, f1.y) ROW1(6, f1.z) ROW1(7, f1.w)
#undef ROW1
            }
        }
        if (c < NCH - 1) {
#pragma unroll
            for (int r = 0; r < 7; r++) {
                int i = tid + r * 256;
                if (i < 1600) {
                    int t = i >> 3, j = i & 7;
                    float* p = sF + ((c + 1) & 1) * (KC * TTd) + (j * 4) * TTd + t;
                    p[0] = pf[r].x; p[TTd] = pf[r].y; p[2 * TTd] = pf[r].z; p[3 * TTd] = pf[r].w;
                }
            }
        }
        __syncthreads();
    }

    // epilogue 1: + c_b, sigmoid, store H1[t][h] (stride 82)
    if (active) {
#pragma unroll
        for (int i = 0; i < 8; i++) {
            int t = rt * 8 + i;
#pragma unroll
            for (int j = 0; j < 4; j++) {
                float2 v = *(float2*)&acc[i][j];
                int h = ch * 8 + 2 * j;
                float s0 = sigf(v.x + scb[h]);
                float s1 = sigf(v.y + scb[h + 1]);
                *(float2*)&sH1[t * 82 + h] = make_float2(s0, s1);
            }
        }
    }
    __syncthreads();

    // -------- GEMM2: acc2[8 t][2 h2-pairs] --------
    unsigned long long acc2[8][2];
#pragma unroll
    for (int i = 0; i < 8; i++) { acc2[i][0] = 0ull; acc2[i][1] = 0ull; }
    float b2r[4], w3r[4];
    if (active) {
#pragma unroll
        for (int jj = 0; jj < 4; jj++) { b2r[jj] = b2[ch * 4 + jj]; w3r[jj] = W3[ch * 4 + jj]; }
#pragma unroll 4
        for (int k = 0; k < H1N; k++) {
            ulonglong2 w2v = *(const ulonglong2*)(sW2t + k * H2N + ch * 4);
#pragma unroll
            for (int i = 0; i < 8; i++) {
                unsigned long long a_ = dup2(sH1[(rt * 8 + i) * 82 + k]);
                fma2(acc2[i][0], a_, w2v.x);
                fma2(acc2[i][1], a_, w2v.y);
            }
        }
        // stage 3 partials: sigmoid(h2)·W3 summed over this thread's 4 h2-cols
#pragma unroll
        for (int i = 0; i < 8; i++) {
            float2 v0 = *(float2*)&acc2[i][0];
            float2 v1 = *(float2*)&acc2[i][1];
            float part = sigf(v0.x + b2r[0]) * w3r[0]
                       + sigf(v0.y + b2r[1]) * w3r[1]
                       + sigf(v1.x + b2r[2]) * w3r[2]
                       + sigf(v1.y + b2r[3]) * w3r[3];
            sPart[ch * TTd + rt * 8 + i] = part;
        }
    }
    __syncthreads();

    // -------- stage 3 reduce + masked softmax over T=200 --------
    float sval = 0.f, mpad = -3.402823466e38f;
    if (tid < TTd) {
        float s = b3[0];
#pragma unroll
        for (int c2 = 0; c2 < 10; c2++) s += sPart[c2 * TTd + tid];
        int mv;
        if (g_maskI32) mv = ((const int*)mask)[(size_t)b * TTd + tid];
        else           mv = (int)mask[(size_t)b * TTd + tid];
        if (!mv) s = NEG_BIG_F;
        sval = s; mpad = s;
    }
    float m = mpad;
#pragma unroll
    for (int o = 16; o; o >>= 1) m = fmaxf(m, __shfl_xor_sync(0xffffffffu, m, o));
    if ((tid & 31) == 0) red[tid >> 5] = m;
    __syncthreads();
    if (tid < 32) {
        float mm = (tid < 8) ? red[tid] : -3.402823466e38f;
#pragma unroll
        for (int o = 4; o; o >>= 1) mm = fmaxf(mm, __shfl_xor_sync(0xffffffffu, mm, o));
        if (tid == 0) red[0] = mm;
    }
    __syncthreads();
    float bmax = red[0];
    float p = (tid < TTd) ? __expf(sval - bmax) : 0.f;
    float ssum = p;
#pragma unroll
    for (int o = 16; o; o >>= 1) ssum += __shfl_xor_sync(0xffffffffu, ssum, o);
    __syncthreads();
    if ((tid & 31) == 0) red[tid >> 5] = ssum;
    __syncthreads();
    if (tid < 32) {
        float ss = (tid < 8) ? red[tid] : 0.f;
#pragma unroll
        for (int o = 4; o; o >>= 1) ss += __shfl_xor_sync(0xffffffffu, ss, o);
        if (tid == 0) red[0] = ss;
    }
    __syncthreads();
    float tot = red[0];
    if (tid < TTd) scoresOut[(size_t)b * TTd + tid] = p / tot;
}

// ============================================================
// Kernel 4: out[b,t,:] = facts[b,t,:] * score[b,t]  (pure stream)
// ============================================================
__global__ void k_scale(const float4* __restrict__ facts4,
                        const float* __restrict__ scores,
                        float4* __restrict__ out4) {
    size_t n4 = (size_t)BB * TTd * (FSZ / 4);
    size_t stride = (size_t)gridDim.x * blockDim.x;
    for (size_t i = (size_t)blockIdx.x * blockDim.x + threadIdx.x; i < n4; i += stride) {
        float s = __ldg(&scores[i >> 5]);
        float4 f = facts4[i];
        out4[i] = make_float4(f.x * s, f.y * s, f.z * s, f.w * s);
    }
}

extern "C" void kernel_launch(void* const* d_in, const int* in_sizes, int n_in,
                              void* d_out, int out_size) {
    const float*         query = (const float*)d_in[0];
    const float*         facts = (const float*)d_in[1];
    const unsigned char* maskp = (const unsigned char*)d_in[2];
    const float*         Wq    = (const float*)d_in[3];
    const float*         bq    = (const float*)d_in[4];
    const float*         aP    = (const float*)d_in[5];
    const float*         W1    = (const float*)d_in[6];
    const float*         b1    = (const float*)d_in[7];
    const float*         W2    = (const float*)d_in[8];
    const float*         b2    = (const float*)d_in[9];
    const float*         W3    = (const float*)d_in[10];
    const float*         b3    = (const float*)d_in[11];

    float* out       = (float*)d_out;
    float* scoresOut = out + (size_t)BB * TTd * FSZ;

    cudaFuncSetAttribute(k_scores, cudaFuncAttributeMaxDynamicSharedMemorySize,
                         SMEM_FLOATS * 4);

    k_detect<<<1, 256>>>(maskp);
    k_prep <<<64, 256>>>(W1, Wq);
    k_query<<<BB, 128>>>(query, bq, aP, b1);
    k_scores<<<BB, 256, SMEM_FLOATS * 4>>>(facts, maskp, W2, b2, W3, b3, scoresOut);
    k_scale<<<6400, 256>>>((const float4*)facts, scoresOut, (float4*)out);
}